// round 9
// baseline (speedup 1.0000x reference)
#include <cuda_runtime.h>

#define N_NODES 2048
#define N_EDGES 4096
#define FV 64
#define FE 16
#define NH 128
#define NC 128

#define ELLW 40
#define MAXPAR 4
#define NBLK 148

// ---------------- scratch (device globals; no allocation) ----------------
__device__ float g_Y[N_NODES * NH];
__device__ float g_tmpN[N_NODES * NH];
__device__ float g_X1F1[N_NODES * 2 * NH];
__device__ float g_X3[N_NODES * NH];
__device__ float g_Yh[N_EDGES * FE];
__device__ float g_Z2F2[N_EDGES * 2 * FE];
__device__ float g_Z4[N_EDGES * FE];
__device__ float g_se[N_EDGES];
__device__ float g_sn[N_NODES];

// adj_v ELL (unordered)
__device__ int   g_vn[N_NODES];
__device__ int   g_vcol[N_NODES * ELLW];
__device__ float g_vval[N_NODES * ELLW];
__device__ int   g_scnt[N_NODES * ELLW];
__device__ int   g_eid[N_NODES * ELLW * MAXPAR];

// adj_e ELL (unordered)
__device__ int      g_en[N_EDGES];
__device__ int      g_ecol[N_EDGES * ELLW];
__device__ float    g_eval[N_EDGES * ELLW];
__device__ float    g_cA[N_EDGES * ELLW];
__device__ float    g_cB[N_EDGES * ELLW];
__device__ float    g_cC[N_EDGES * ELLW];
__device__ float    g_adjEv[N_EDGES * ELLW];
__device__ unsigned g_cmaxb[N_EDGES];

// edge endpoints from T
__device__ int   g_Ea[N_EDGES];
__device__ int   g_Eb[N_EDGES];
__device__ float g_Ewa[N_EDGES];
__device__ float g_Ewb[N_EDGES];
__device__ int   g_Ecnt[N_EDGES];

// grid barrier counter
__device__ unsigned g_barCnt;

// ---------------- init ----------------
__global__ void k_init() {
    int i = blockIdx.x * blockDim.x + threadIdx.x;
    if (i == 0) g_barCnt = 0u;
    if (i < N_EDGES) {
        g_Ecnt[i] = 0; g_Ea[i] = 0; g_Eb[i] = -1;
        g_Ewa[i] = 0.f; g_Ewb[i] = 0.f;
        g_en[i] = 0;
        if (i < N_NODES) g_vn[i] = 0;
    }
    for (int j = i; j < N_NODES * ELLW; j += gridDim.x * blockDim.x) g_scnt[j] = 0;
}

// ---------------- fused dense scan: T + adjV + adjE -> structures ----------------
#define T4_CNT   (N_NODES * N_EDGES / 4)
#define V4_CNT   (N_NODES * N_NODES / 4)
#define E4_CNT   (N_EDGES * N_EDGES / 4)
#define TOTAL4   (T4_CNT + V4_CNT + E4_CNT)

__device__ __forceinline__ float4 scan_load(const float4* T4, const float4* V4,
                                            const float4* E4, int idx) {
    const float4* p; int li;
    if (idx < T4_CNT)               { p = T4; li = idx; }
    else if (idx < T4_CNT + V4_CNT) { p = V4; li = idx - T4_CNT; }
    else                            { p = E4; li = idx - T4_CNT - V4_CNT; }
    return __ldg(p + li);
}

__device__ __forceinline__ void scan_proc(float4 v, int idx) {
    if (v.x == 0.f && v.y == 0.f && v.z == 0.f && v.w == 0.f) return;
    float vv[4] = {v.x, v.y, v.z, v.w};
    if (idx < T4_CNT) {
        int n = idx >> 10;
        int e0 = (idx & 1023) * 4;
#pragma unroll
        for (int s = 0; s < 4; s++) {
            if (vv[s] != 0.f) {
                int e = e0 + s;
                int slot = atomicAdd(&g_Ecnt[e], 1);
                if (slot == 0) { g_Ea[e] = n; g_Ewa[e] = vv[s]; }
                else           { g_Eb[e] = n; g_Ewb[e] = vv[s]; }
            }
        }
    } else if (idx < T4_CNT + V4_CNT) {
        int i = idx - T4_CNT;
        int r = i >> 9;
        int c0 = (i & 511) * 4;
#pragma unroll
        for (int s = 0; s < 4; s++) {
            if (vv[s] != 0.f) {
                int slot = atomicAdd(&g_vn[r], 1);
                if (slot < ELLW) {
                    g_vcol[r * ELLW + slot] = c0 + s;
                    g_vval[r * ELLW + slot] = vv[s];
                }
            }
        }
    } else {
        int i = idx - T4_CNT - V4_CNT;
        int r = i >> 10;
        int c0 = (i & 1023) * 4;
#pragma unroll
        for (int s = 0; s < 4; s++) {
            if (vv[s] != 0.f) {
                int slot = atomicAdd(&g_en[r], 1);
                if (slot < ELLW) {
                    g_ecol[r * ELLW + slot] = c0 + s;
                    g_eval[r * ELLW + slot] = vv[s];
                }
            }
        }
    }
}

__global__ void k_scan_all(const float4* __restrict__ T4,
                           const float4* __restrict__ V4,
                           const float4* __restrict__ E4) {
    int stride = gridDim.x * blockDim.x;
    int i = blockIdx.x * blockDim.x + threadIdx.x;
    // MLP-4 batches of independent strided loads
    for (; i + 3 * stride < TOTAL4; i += 4 * stride) {
        float4 v0 = scan_load(T4, V4, E4, i);
        float4 v1 = scan_load(T4, V4, E4, i + stride);
        float4 v2 = scan_load(T4, V4, E4, i + 2 * stride);
        float4 v3 = scan_load(T4, V4, E4, i + 3 * stride);
        scan_proc(v0, i);
        scan_proc(v1, i + stride);
        scan_proc(v2, i + 2 * stride);
        scan_proc(v3, i + 3 * stride);
    }
    for (; i < TOTAL4; i += stride) scan_proc(scan_load(T4, V4, E4, i), i);
}

// ---------------- grid barrier (monotonic counter; reset each launch by k_init) ----
__device__ __forceinline__ void grid_bar(unsigned target) {
    __syncthreads();
    if (threadIdx.x == 0) {
        __threadfence();
        atomicAdd(&g_barCnt, 1u);
        volatile unsigned* p = &g_barCnt;
        while (*p < target) { __nanosleep(32); }
        __threadfence();
    }
    __syncthreads();
}

// ---------------- device stage helpers ----------------
__device__ __forceinline__ void link_one(int r, int c, int e) {
    int n = g_vn[r]; if (n > ELLW) n = ELLW;
    int base = r * ELLW;
    for (int i = 0; i < n; i++) {
        if (g_vcol[base + i] == c) {
            int p = atomicAdd(&g_scnt[base + i], 1);
            if (p < MAXPAR) g_eid[(base + i) * MAXPAR + p] = e;
            return;
        }
    }
}

__device__ __forceinline__ void dev_link_ecoef(int e) {
    int a = g_Ea[e], b = g_Eb[e];
    float wa = g_Ewa[e], wb = g_Ewb[e];
    if (b >= 0 && a != b) { link_one(a, b, e); link_one(b, a, e); }
    int n = g_en[e]; if (n > ELLW) n = ELLW;
    size_t base = (size_t)e * ELLW;
    for (int i = 0; i < n; i++) {
        int f = g_ecol[base + i];
        float ev = g_eval[base + i];
        float cA = 0.f, cB = 0.f, cC = 0.f;
        if (f == e) {
            cC = ev;
        } else {
            int c = g_Ea[f], d = g_Eb[f];
            float wc = g_Ewa[f], wd = g_Ewb[f];
            float ma = 0.f, mb = 0.f;
            if (a == c) ma += wc;
            if (d >= 0 && a == d) ma += wd;
            if (b >= 0) {
                if (b == c) mb += wc;
                if (d >= 0 && b == d) mb += wd;
            }
            cA = ev * wa * ma;
            cB = ev * wb * mb;
        }
        g_cA[base + i] = cA; g_cB[base + i] = cB; g_cC[base + i] = cC;
    }
}

// register-B GEMM tile: 16 rows x 128 cols of C = A[.,K] @ B[K,128]
__device__ __forceinline__ void dev_gemm_rb(const float* __restrict__ A,
                                            const float* __restrict__ B,
                                            float* __restrict__ C,
                                            int K, int rowBase) {
    int col = threadIdx.x & 127;
    int half = threadIdx.x >> 7;
    float acc[8];
#pragma unroll
    for (int r = 0; r < 8; r++) acc[r] = 0.f;
    for (int kc = 0; kc < K; kc += 64) {
        float breg[64];
#pragma unroll
        for (int k = 0; k < 64; k++) breg[k] = B[(size_t)(kc + k) * 128 + col];
#pragma unroll
        for (int r = 0; r < 8; r++) {
            int row = rowBase + r * 2 + half;
            const float4* a4 = (const float4*)(A + (size_t)row * K + kc);
            float s = 0.f;
#pragma unroll
            for (int k4 = 0; k4 < 16; k4++) {
                float4 a = a4[k4];
                s += a.x * breg[4 * k4 + 0];
                s += a.y * breg[4 * k4 + 1];
                s += a.z * breg[4 * k4 + 2];
                s += a.w * breg[4 * k4 + 3];
            }
            acc[r] += s;
        }
    }
#pragma unroll
    for (int r = 0; r < 8; r++)
        C[(size_t)(rowBase + r * 2 + half) * 128 + col] = acc[r];
}

__device__ __forceinline__ void dev_gate_warp(const float* __restrict__ H,
                                              const float* __restrict__ p,
                                              float* __restrict__ s, int row, int K) {
    int lane = threadIdx.x & 31;
    float acc = 0.f;
    for (int k = lane; k < K; k += 32) acc += H[(size_t)row * K + k] * p[k];
    for (int o = 16; o; o >>= 1) acc += __shfl_xor_sync(0xffffffffu, acc, o);
    if (lane == 0) s[row] = acc;
}

__device__ __forceinline__ void dev_gate_thread(const float* __restrict__ H,
                                                const float* __restrict__ p,
                                                float* __restrict__ s, int row, int K) {
    const float4* h4 = (const float4*)(H + (size_t)row * K);
    const float4* p4 = (const float4*)p;
    float acc = 0.f;
    for (int i = 0; i < K / 4; i++) {
        float4 a = h4[i], b = p4[i];
        acc += a.x * b.x + a.y * b.y + a.z * b.z + a.w * b.w;
    }
    s[row] = acc;
}

__device__ __forceinline__ void dev_node_spmm(const float* __restrict__ Y,
                                              const float* __restrict__ bias,
                                              const float* __restrict__ se,
                                              float* __restrict__ out,
                                              int ldo, int do_relu, int row, int c) {
    int n = g_vn[row]; if (n > ELLW) n = ELLW;
    int base = row * ELLW;
    float acc = bias[c];
    for (int i = 0; i < n; i++) {
        int col = g_vcol[base + i];
        float val = g_vval[base + i];
        float mult;
        if (col == row) {
            mult = 1.f;
        } else {
            int cnt = g_scnt[base + i];
            if (cnt > MAXPAR) cnt = MAXPAR;
            mult = 0.f;
            for (int q = 0; q < cnt; q++) mult += se[g_eid[(base + i) * MAXPAR + q]];
        }
        acc += val * mult * Y[(size_t)col * NH + c];
    }
    if (do_relu) acc = fmaxf(acc, 0.f);
    out[(size_t)row * ldo + c] = acc;
}

__device__ __forceinline__ void dev_ln_relu128(const float* __restrict__ in,
                                               const float* __restrict__ g,
                                               const float* __restrict__ b,
                                               float* __restrict__ out,
                                               int row, int ldo) {
    int lane = threadIdx.x & 31;
    float v[4];
    float sum = 0.f;
#pragma unroll
    for (int i = 0; i < 4; i++) {
        v[i] = in[(size_t)row * 128 + lane + 32 * i];
        sum += v[i];
    }
    for (int o = 16; o; o >>= 1) sum += __shfl_xor_sync(0xffffffffu, sum, o);
    float mean = sum * (1.f / 128.f);
    float var = 0.f;
#pragma unroll
    for (int i = 0; i < 4; i++) { float d = v[i] - mean; var += d * d; }
    for (int o = 16; o; o >>= 1) var += __shfl_xor_sync(0xffffffffu, var, o);
    float rstd = rsqrtf(var * (1.f / 128.f) + 1e-5f);
#pragma unroll
    for (int i = 0; i < 4; i++) {
        int idx = lane + 32 * i;
        float y = (v[i] - mean) * rstd * g[idx] + b[idx];
        out[(size_t)row * ldo + idx] = fmaxf(y, 0.f);
    }
}

__device__ __forceinline__ void dev_edge_vals(const float* __restrict__ sn, int e) {
    float sa = sn[g_Ea[e]];
    int b = g_Eb[e];
    float sb = (b >= 0) ? sn[b] : 0.f;
    int n = g_en[e]; if (n > ELLW) n = ELLW;
    size_t base = (size_t)e * ELLW;
    for (int i = 0; i < n; i++) {
        float v = g_cC[base + i] + g_cA[base + i] * sa + g_cB[base + i] * sb;
        g_adjEv[base + i] = v;
        if (v > 0.f) atomicMax(&g_cmaxb[g_ecol[base + i]], __float_as_uint(v));
    }
}

__device__ __forceinline__ void dev_edge_spmm(const float* __restrict__ Yh,
                                              const float* __restrict__ bias,
                                              float* __restrict__ out,
                                              int ldo, int r, int c) {
    int n = g_en[r]; if (n > ELLW) n = ELLW;
    size_t base = (size_t)r * ELLW;
    float acc = bias[c];
    for (int i = 0; i < n; i++) {
        int f = g_ecol[base + i];
        float w = g_adjEv[base + i] / __uint_as_float(g_cmaxb[f]);
        acc += w * Yh[(size_t)f * FE + c];
    }
    out[(size_t)r * ldo + c] = fmaxf(acc, 0.f);
}

__device__ __forceinline__ void dev_mlp2(const float* __restrict__ Z,
                                         const float* __restrict__ W2,
                                         const float* __restrict__ Wf2,
                                         const float* __restrict__ g2,
                                         const float* __restrict__ be2,
                                         float* __restrict__ Yh,
                                         float* __restrict__ Z2F2,
                                         float* sh, int rowBase) {
    float* sW = sh;         // 256
    float* sF = sh + 256;   // 256
    int tid = threadIdx.x;
    sW[tid] = W2[tid];
    sF[tid] = Wf2[tid];
    __syncthreads();
    int c = tid & 15;
    int r = rowBase + (tid >> 4);
    float zc = Z[(size_t)r * 16 + c];
    float a1 = 0.f, a2 = 0.f;
#pragma unroll
    for (int k = 0; k < 16; k++) {
        float zk = __shfl_sync(0xffffffffu, zc, k, 16);
        a1 += fmaxf(zk, 0.f) * sW[k * 16 + c];
        a2 += zk * sF[k * 16 + c];
    }
    Yh[(size_t)r * 16 + c] = a1;
    float sum = a2;
    for (int o = 8; o; o >>= 1) sum += __shfl_xor_sync(0xffffffffu, sum, o, 16);
    float mean = sum * (1.f / 16.f);
    float d = a2 - mean;
    float var = d * d;
    for (int o = 8; o; o >>= 1) var += __shfl_xor_sync(0xffffffffu, var, o, 16);
    float rstd = rsqrtf(var * (1.f / 16.f) + 1e-5f);
    float y = d * rstd * g2[c] + be2[c];
    Z2F2[(size_t)r * 32 + 16 + c] = fmaxf(y, 0.f);
    __syncthreads();
}

__device__ __forceinline__ void dev_mlp4(const float* __restrict__ A,
                                         const float* __restrict__ W4,
                                         float* __restrict__ Yh,
                                         float* sh, int rowBase) {
    float* sW = sh;  // 32x16 = 512
    int tid = threadIdx.x;
    sW[(tid >> 4) * 16 + (tid & 15)] = W4[tid];
    sW[(16 + (tid >> 4)) * 16 + (tid & 15)] = W4[256 + tid];
    __syncthreads();
    int c = tid & 15;
    int r = rowBase + (tid >> 4);
    float z0 = A[(size_t)r * 32 + c];
    float z1 = A[(size_t)r * 32 + 16 + c];
    float a = 0.f;
#pragma unroll
    for (int k = 0; k < 16; k++) {
        a += __shfl_sync(0xffffffffu, z0, k, 16) * sW[k * 16 + c];
        a += __shfl_sync(0xffffffffu, z1, k, 16) * sW[(16 + k) * 16 + c];
    }
    Yh[(size_t)r * 16 + c] = a;
    __syncthreads();
}

// ---------------- the persistent mega-kernel ----------------
__global__ void __launch_bounds__(256)
k_mega(const float* __restrict__ X, const float* __restrict__ Z,
       const float* __restrict__ W1, const float* __restrict__ p1, const float* __restrict__ b1,
       const float* __restrict__ Wf1, const float* __restrict__ g1, const float* __restrict__ be1,
       const float* __restrict__ W2, const float* __restrict__ p2, const float* __restrict__ b2,
       const float* __restrict__ Wf2, const float* __restrict__ g2, const float* __restrict__ be2,
       const float* __restrict__ W3, const float* __restrict__ p3, const float* __restrict__ b3,
       const float* __restrict__ W4, const float* __restrict__ p4, const float* __restrict__ b4,
       const float* __restrict__ W5, const float* __restrict__ p5, const float* __restrict__ b5,
       float* __restrict__ out) {
    __shared__ float sh[512];
    int tid = threadIdx.x;
    unsigned tgt = 0;

    // ---- S0: link+ecoef | gate1(se=Z.p1) | mlp2(Yh,F2) | gemm1 dual | cmax zero ----
    for (int vb = blockIdx.x; vb < 560; vb += NBLK) {
        if (vb < 256) {
            int mat = vb >> 7;
            int rowBase = (vb & 127) * 16;
            dev_gemm_rb(X, mat ? Wf1 : W1, mat ? g_tmpN : g_Y, FV, rowBase);
        } else if (vb < 512) {
            dev_mlp2(Z, W2, Wf2, g2, be2, g_Yh, g_Z2F2, sh, (vb - 256) * 16);
        } else if (vb < 528) {
            dev_link_ecoef((vb - 512) * 256 + tid);
        } else if (vb < 544) {
            dev_gate_thread(Z, p1, g_se, (vb - 528) * 256 + tid, FE);
        } else {
            g_cmaxb[(vb - 544) * 256 + tid] = 0u;
        }
    }
    tgt += NBLK; grid_bar(tgt);

    // ---- S1: node_spmm1 -> X1 | ln_relu -> F1 ----
    for (int vb = blockIdx.x; vb < 1280; vb += NBLK) {
        if (vb < 1024) {
            int row = vb * 2 + (tid >> 7);
            dev_node_spmm(g_Y, b1, g_se, g_X1F1, 2 * NH, 1, row, tid & 127);
        } else {
            int row = (vb - 1024) * 8 + (tid >> 5);
            dev_ln_relu128(g_tmpN, g1, be1, g_X1F1 + NH, row, 2 * NH);
        }
    }
    tgt += NBLK; grid_bar(tgt);

    // ---- S2: gate2(sn=X1F1.p2) | gemm3(tmpN = X1F1@W3) ----
    for (int vb = blockIdx.x; vb < 384; vb += NBLK) {
        if (vb < 256) {
            int row = vb * 8 + (tid >> 5);
            dev_gate_warp(g_X1F1, p2, g_sn, row, 2 * NH);
        } else {
            dev_gemm_rb(g_X1F1, W3, g_tmpN, 2 * NH, (vb - 256) * 16);
        }
    }
    tgt += NBLK; grid_bar(tgt);

    // ---- S3: edge_vals(layer2) ----
    for (int vb = blockIdx.x; vb < 16; vb += NBLK)
        dev_edge_vals(g_sn, vb * 256 + tid);
    tgt += NBLK; grid_bar(tgt);

    // ---- S4: edge_spmm2 -> Z2 ----
    for (int vb = blockIdx.x; vb < 256; vb += NBLK)
        dev_edge_spmm(g_Yh, b2, g_Z2F2, 2 * FE, vb * 16 + (tid >> 4), tid & 15);
    tgt += NBLK; grid_bar(tgt);

    // ---- S5: gate3(se=Z2F2.p3) | mlp4(Yh) | cmax zero ----
    for (int vb = blockIdx.x; vb < 288; vb += NBLK) {
        if (vb < 16) {
            dev_gate_thread(g_Z2F2, p3, g_se, vb * 256 + tid, 2 * FE);
        } else if (vb < 272) {
            dev_mlp4(g_Z2F2, W4, g_Yh, sh, (vb - 16) * 16);
        } else {
            g_cmaxb[(vb - 272) * 256 + tid] = 0u;
        }
    }
    tgt += NBLK; grid_bar(tgt);

    // ---- S6: node_spmm3 -> X3 ----
    for (int vb = blockIdx.x; vb < 1024; vb += NBLK) {
        int row = vb * 2 + (tid >> 7);
        dev_node_spmm(g_tmpN, b3, g_se, g_X3, NH, 1, row, tid & 127);
    }
    tgt += NBLK; grid_bar(tgt);

    // ---- S7: gate4(sn=X3.p4) | gemm5(tmpN = X3@W5) ----
    for (int vb = blockIdx.x; vb < 384; vb += NBLK) {
        if (vb < 256) {
            int row = vb * 8 + (tid >> 5);
            dev_gate_warp(g_X3, p4, g_sn, row, NH);
        } else {
            dev_gemm_rb(g_X3, W5, g_tmpN, NH, (vb - 256) * 16);
        }
    }
    tgt += NBLK; grid_bar(tgt);

    // ---- S8: edge_vals(layer4) ----
    for (int vb = blockIdx.x; vb < 16; vb += NBLK)
        dev_edge_vals(g_sn, vb * 256 + tid);
    tgt += NBLK; grid_bar(tgt);

    // ---- S9: edge_spmm4 -> Z4 ----
    for (int vb = blockIdx.x; vb < 256; vb += NBLK)
        dev_edge_spmm(g_Yh, b4, g_Z4, FE, vb * 16 + (tid >> 4), tid & 15);
    tgt += NBLK; grid_bar(tgt);

    // ---- S10: gate5(se=Z4.p5) ----
    for (int vb = blockIdx.x; vb < 16; vb += NBLK)
        dev_gate_thread(g_Z4, p5, g_se, vb * 256 + tid, FE);
    tgt += NBLK; grid_bar(tgt);

    // ---- S11: node_spmm5 -> out (no relu) ----
    for (int vb = blockIdx.x; vb < 1024; vb += NBLK) {
        int row = vb * 2 + (tid >> 7);
        dev_node_spmm(g_tmpN, b5, g_se, out, NC, 0, row, tid & 127);
    }
}

// ---------------- host ----------------
extern "C" void kernel_launch(void* const* d_in, const int* in_sizes, int n_in,
                              void* d_out, int out_size) {
    const float* X    = (const float*)d_in[0];
    const float* Z    = (const float*)d_in[1];
    const float* adjE = (const float*)d_in[2];
    const float* adjV = (const float*)d_in[3];
    const float* T    = (const float*)d_in[4];
    const float* W1  = (const float*)d_in[5];
    const float* p1  = (const float*)d_in[6];
    const float* b1  = (const float*)d_in[7];
    const float* Wf1 = (const float*)d_in[8];
    const float* g1  = (const float*)d_in[9];
    const float* be1 = (const float*)d_in[10];
    const float* W2  = (const float*)d_in[11];
    const float* p2  = (const float*)d_in[12];
    const float* b2  = (const float*)d_in[13];
    const float* Wf2 = (const float*)d_in[14];
    const float* g2  = (const float*)d_in[15];
    const float* be2 = (const float*)d_in[16];
    const float* W3  = (const float*)d_in[17];
    const float* p3  = (const float*)d_in[18];
    const float* b3  = (const float*)d_in[19];
    const float* W4  = (const float*)d_in[20];
    const float* p4  = (const float*)d_in[21];
    const float* b4  = (const float*)d_in[22];
    const float* W5  = (const float*)d_in[23];
    const float* p5  = (const float*)d_in[24];
    const float* b5  = (const float*)d_in[25];
    float* out = (float*)d_out;

    k_init<<<320, 256>>>();
    k_scan_all<<<2048, 256>>>((const float4*)T, (const float4*)adjV, (const float4*)adjE);
    k_mega<<<NBLK, 256>>>(X, Z,
                          W1, p1, b1, Wf1, g1, be1,
                          W2, p2, b2, Wf2, g2, be2,
                          W3, p3, b3, W4, p4, b4,
                          W5, p5, b5, out);
}

// round 10
// speedup vs baseline: 1.4596x; 1.4596x over previous
#include <cuda_runtime.h>

#define N_NODES 2048
#define N_EDGES 4096
#define FV 64
#define FE 16
#define NH 128
#define NC 128

#define ELLW 40
#define MAXPAR 4

// ---------------- scratch (device globals; no allocation) ----------------
__device__ float g_Y[N_NODES * NH];
__device__ float g_tmpN[N_NODES * NH];
__device__ float g_X1F1[N_NODES * 2 * NH];
__device__ float g_X3[N_NODES * NH];
__device__ float g_Yh[N_EDGES * FE];
__device__ float g_Z2F2[N_EDGES * 2 * FE];
__device__ float g_Z4[N_EDGES * FE];

// gates (se1/se5 written fully; se3/sn2/sn4 accumulated -> zeroed in init)
__device__ float g_se1[N_EDGES];
__device__ float g_se3[N_EDGES];
__device__ float g_se5[N_EDGES];
__device__ float g_sn2[N_NODES];
__device__ float g_sn4[N_NODES];

// adj_v ELL (unordered)
__device__ int   g_vn[N_NODES];
__device__ int   g_vcol[N_NODES * ELLW];
__device__ float g_vval[N_NODES * ELLW];
__device__ int   g_scnt[N_NODES * ELLW];
__device__ int   g_eid[N_NODES * ELLW * MAXPAR];

// adj_e ELL (unordered)
__device__ int      g_en[N_EDGES];
__device__ int      g_ecol[N_EDGES * ELLW];
__device__ float    g_eval[N_EDGES * ELLW];
__device__ float    g_cA[N_EDGES * ELLW];
__device__ float    g_cB[N_EDGES * ELLW];
__device__ float    g_cC[N_EDGES * ELLW];
__device__ float    g_adjEv[N_EDGES * ELLW];
__device__ unsigned g_cmax2[N_EDGES];
__device__ unsigned g_cmax4[N_EDGES];

// edge endpoints from T
__device__ int   g_Ea[N_EDGES];
__device__ int   g_Eb[N_EDGES];
__device__ float g_Ewa[N_EDGES];
__device__ float g_Ewb[N_EDGES];
__device__ int   g_Ecnt[N_EDGES];

// ---------------- init: zero all accumulated state ----------------
__global__ void k_init() {
    int stride = gridDim.x * blockDim.x;
    for (int i = blockIdx.x * blockDim.x + threadIdx.x; i < N_NODES * ELLW; i += stride)
        g_scnt[i] = 0;
    for (int i = blockIdx.x * blockDim.x + threadIdx.x; i < N_EDGES; i += stride) {
        g_Ecnt[i] = 0; g_Ea[i] = 0; g_Eb[i] = -1;
        g_Ewa[i] = 0.f; g_Ewb[i] = 0.f;
        g_en[i] = 0;
        g_se3[i] = 0.f;
        g_cmax2[i] = 0u; g_cmax4[i] = 0u;
        if (i < N_NODES) { g_vn[i] = 0; g_sn2[i] = 0.f; g_sn4[i] = 0.f; }
    }
}

// ---------------- fused dense scan: T + adjV + adjE -> structures ----------------
#define T4_CNT   (N_NODES * N_EDGES / 4)
#define V4_CNT   (N_NODES * N_NODES / 4)
#define E4_CNT   (N_EDGES * N_EDGES / 4)
#define TOTAL4   (T4_CNT + V4_CNT + E4_CNT)

__device__ __forceinline__ float4 scan_load(const float4* T4, const float4* V4,
                                            const float4* E4, int idx) {
    const float4* p; int li;
    if (idx < T4_CNT)               { p = T4; li = idx; }
    else if (idx < T4_CNT + V4_CNT) { p = V4; li = idx - T4_CNT; }
    else                            { p = E4; li = idx - T4_CNT - V4_CNT; }
    return __ldg(p + li);
}

__device__ __forceinline__ void scan_proc(float4 v, int idx) {
    if (v.x == 0.f && v.y == 0.f && v.z == 0.f && v.w == 0.f) return;
    float vv[4] = {v.x, v.y, v.z, v.w};
    if (idx < T4_CNT) {
        int n = idx >> 10;
        int e0 = (idx & 1023) * 4;
#pragma unroll
        for (int s = 0; s < 4; s++) {
            if (vv[s] != 0.f) {
                int e = e0 + s;
                int slot = atomicAdd(&g_Ecnt[e], 1);
                if (slot == 0) { g_Ea[e] = n; g_Ewa[e] = vv[s]; }
                else           { g_Eb[e] = n; g_Ewb[e] = vv[s]; }
            }
        }
    } else if (idx < T4_CNT + V4_CNT) {
        int i = idx - T4_CNT;
        int r = i >> 9;
        int c0 = (i & 511) * 4;
#pragma unroll
        for (int s = 0; s < 4; s++) {
            if (vv[s] != 0.f) {
                int slot = atomicAdd(&g_vn[r], 1);
                if (slot < ELLW) {
                    g_vcol[r * ELLW + slot] = c0 + s;
                    g_vval[r * ELLW + slot] = vv[s];
                }
            }
        }
    } else {
        int i = idx - T4_CNT - V4_CNT;
        int r = i >> 10;
        int c0 = (i & 1023) * 4;
#pragma unroll
        for (int s = 0; s < 4; s++) {
            if (vv[s] != 0.f) {
                int slot = atomicAdd(&g_en[r], 1);
                if (slot < ELLW) {
                    g_ecol[r * ELLW + slot] = c0 + s;
                    g_eval[r * ELLW + slot] = vv[s];
                }
            }
        }
    }
}

__global__ void k_scan_all(const float4* __restrict__ T4,
                           const float4* __restrict__ V4,
                           const float4* __restrict__ E4) {
    int stride = gridDim.x * blockDim.x;
    int i = blockIdx.x * blockDim.x + threadIdx.x;
    for (; i + 3 * stride < TOTAL4; i += 4 * stride) {
        float4 v0 = scan_load(T4, V4, E4, i);
        float4 v1 = scan_load(T4, V4, E4, i + stride);
        float4 v2 = scan_load(T4, V4, E4, i + 2 * stride);
        float4 v3 = scan_load(T4, V4, E4, i + 3 * stride);
        scan_proc(v0, i);
        scan_proc(v1, i + stride);
        scan_proc(v2, i + 2 * stride);
        scan_proc(v3, i + 3 * stride);
    }
    for (; i < TOTAL4; i += stride) scan_proc(scan_load(T4, V4, E4, i), i);
}

// ---------------- link edges into adj_v slots + adj_e coef precompute ----------------
__device__ __forceinline__ void link_one(int r, int c, int e) {
    int n = g_vn[r]; if (n > ELLW) n = ELLW;
    int base = r * ELLW;
    for (int i = 0; i < n; i++) {
        if (g_vcol[base + i] == c) {
            int p = atomicAdd(&g_scnt[base + i], 1);
            if (p < MAXPAR) g_eid[(base + i) * MAXPAR + p] = e;
            return;
        }
    }
}
__global__ void k_link_ecoef() {
    int e = blockIdx.x * blockDim.x + threadIdx.x;
    if (e >= N_EDGES) return;
    int a = g_Ea[e], b = g_Eb[e];
    float wa = g_Ewa[e], wb = g_Ewb[e];
    if (b >= 0 && a != b) { link_one(a, b, e); link_one(b, a, e); }
    int n = g_en[e]; if (n > ELLW) n = ELLW;
    size_t base = (size_t)e * ELLW;
    for (int i = 0; i < n; i++) {
        int f = g_ecol[base + i];
        float ev = g_eval[base + i];
        float cA = 0.f, cB = 0.f, cC = 0.f;
        if (f == e) {
            cC = ev;
        } else {
            int c = g_Ea[f], d = g_Eb[f];
            float wc = g_Ewa[f], wd = g_Ewb[f];
            float ma = 0.f, mb = 0.f;
            if (a == c) ma += wc;
            if (d >= 0 && a == d) ma += wd;
            if (b >= 0) {
                if (b == c) mb += wc;
                if (d >= 0 && b == d) mb += wd;
            }
            cA = ev * wa * ma;
            cB = ev * wb * mb;
        }
        g_cA[base + i] = cA; g_cB[base + i] = cB; g_cC[base + i] = cC;
    }
}

// ---------------- slot-parallel edge multiplier values + column max ----------------
__global__ void k_edge_vals(const float* __restrict__ sn, unsigned* __restrict__ cmax) {
    int idx = blockIdx.x * blockDim.x + threadIdx.x;
    if (idx >= N_EDGES * ELLW) return;
    int e = idx / ELLW;
    int i = idx - e * ELLW;
    int n = g_en[e]; if (n > ELLW) n = ELLW;
    if (i >= n) return;
    float sa = sn[g_Ea[e]];
    int b = g_Eb[e];
    float sb = (b >= 0) ? sn[b] : 0.f;
    float v = g_cC[idx] + g_cA[idx] * sa + g_cB[idx] * sb;
    g_adjEv[idx] = v;
    if (v > 0.f) atomicMax(&cmax[g_ecol[idx]], __float_as_uint(v));
}

// ---------------- register-B GEMM: C[M,128] = A[M,K] @ B[K,128] ----------------
__global__ void __launch_bounds__(256, 2)
k_gemmRB(const float* __restrict__ A,
         const float* __restrict__ B1, const float* __restrict__ B2,
         float* __restrict__ C1, float* __restrict__ C2, int K) {
    const float* __restrict__ B = blockIdx.y ? B2 : B1;
    float* __restrict__ C = blockIdx.y ? C2 : C1;
    int col = threadIdx.x & 127;
    int half = threadIdx.x >> 7;
    int rowBase = blockIdx.x * 16;
    float acc[8];
#pragma unroll
    for (int r = 0; r < 8; r++) acc[r] = 0.f;
    for (int kc = 0; kc < K; kc += 64) {
        float breg[64];
#pragma unroll
        for (int k = 0; k < 64; k++) breg[k] = B[(size_t)(kc + k) * 128 + col];
#pragma unroll
        for (int r = 0; r < 8; r++) {
            int row = rowBase + r * 2 + half;
            const float4* a4 = (const float4*)(A + (size_t)row * K + kc);
            float s = 0.f;
#pragma unroll
            for (int k4 = 0; k4 < 16; k4++) {
                float4 a = a4[k4];
                s += a.x * breg[4 * k4 + 0];
                s += a.y * breg[4 * k4 + 1];
                s += a.z * breg[4 * k4 + 2];
                s += a.w * breg[4 * k4 + 3];
            }
            acc[r] += s;
        }
    }
#pragma unroll
    for (int r = 0; r < 8; r++)
        C[(size_t)(rowBase + r * 2 + half) * 128 + col] = acc[r];
}

// ---------------- layernorm + relu -> F1, + partial sn2 (cols 128..255 of p2) ------
__global__ void k_ln_relu(const float* __restrict__ in, const float* __restrict__ g,
                          const float* __restrict__ b, const float* __restrict__ p2,
                          float* __restrict__ out) {
    int w = (blockIdx.x * blockDim.x + threadIdx.x) >> 5;   // row
    int lane = threadIdx.x & 31;
    if (w >= N_NODES) return;
    float v[4];
    float sum = 0.f;
#pragma unroll
    for (int i = 0; i < 4; i++) {
        v[i] = in[(size_t)w * 128 + lane + 32 * i];
        sum += v[i];
    }
    for (int o = 16; o; o >>= 1) sum += __shfl_xor_sync(0xffffffffu, sum, o);
    float mean = sum * (1.f / 128.f);
    float var = 0.f;
#pragma unroll
    for (int i = 0; i < 4; i++) { float d = v[i] - mean; var += d * d; }
    for (int o = 16; o; o >>= 1) var += __shfl_xor_sync(0xffffffffu, var, o);
    float rstd = rsqrtf(var * (1.f / 128.f) + 1e-5f);
    float dotp = 0.f;
#pragma unroll
    for (int i = 0; i < 4; i++) {
        int idx = lane + 32 * i;
        float y = (v[i] - mean) * rstd * g[idx] + b[idx];
        y = fmaxf(y, 0.f);
        out[(size_t)w * 256 + idx] = y;
        dotp += y * p2[128 + idx];
    }
    for (int o = 16; o; o >>= 1) dotp += __shfl_xor_sync(0xffffffffu, dotp, o);
    if (lane == 0) atomicAdd(&g_sn2[w], dotp);
}

// ---------------- fused edge MLP (layer 2) + se1 + partial se3 ----------------
// per row r: Yh = relu(Z)@W2 ; F2 = relu(LN(Z@Wf2)) -> Z2F2[:,16:32)
// se1[r] = dot(Z[r], p1) ; se3[r] += dot(F2[r], p3[16:32))
__global__ void k_edge_mlp2(const float* __restrict__ Z, const float* __restrict__ W2,
                            const float* __restrict__ Wf2, const float* __restrict__ g2,
                            const float* __restrict__ be2, const float* __restrict__ p1,
                            const float* __restrict__ p3,
                            float* __restrict__ Yh, float* __restrict__ Z2F2) {
    __shared__ float sW[256], sF[256];
    int tid = threadIdx.x;
    sW[tid] = W2[tid];
    sF[tid] = Wf2[tid];
    __syncthreads();
    int c = tid & 15;
    int r = blockIdx.x * 16 + (tid >> 4);
    float zc = Z[(size_t)r * 16 + c];
    float a1 = 0.f, a2 = 0.f;
#pragma unroll
    for (int k = 0; k < 16; k++) {
        float zk = __shfl_sync(0xffffffffu, zc, k, 16);
        a1 += fmaxf(zk, 0.f) * sW[k * 16 + c];
        a2 += zk * sF[k * 16 + c];
    }
    Yh[(size_t)r * 16 + c] = a1;
    // se1 = dot(Z row, p1)
    float d1 = zc * p1[c];
    for (int o = 8; o; o >>= 1) d1 += __shfl_xor_sync(0xffffffffu, d1, o, 16);
    if (c == 0) g_se1[r] = d1;
    // layernorm of a2
    float sum = a2;
    for (int o = 8; o; o >>= 1) sum += __shfl_xor_sync(0xffffffffu, sum, o, 16);
    float mean = sum * (1.f / 16.f);
    float d = a2 - mean;
    float var = d * d;
    for (int o = 8; o; o >>= 1) var += __shfl_xor_sync(0xffffffffu, var, o, 16);
    float rstd = rsqrtf(var * (1.f / 16.f) + 1e-5f);
    float y = fmaxf(d * rstd * g2[c] + be2[c], 0.f);
    Z2F2[(size_t)r * 32 + 16 + c] = y;
    // partial se3 from F2
    float d3 = y * p3[16 + c];
    for (int o = 8; o; o >>= 1) d3 += __shfl_xor_sync(0xffffffffu, d3, o, 16);
    if (c == 0) atomicAdd(&g_se3[r], d3);
}

// ---------------- edge MLP (layer 4): Yh = Z2F2[E,32] @ W4[32,16] ----------------
__global__ void k_edge_mlp4(const float* __restrict__ A, const float* __restrict__ W4,
                            float* __restrict__ Yh) {
    __shared__ float sW[512];
    int tid = threadIdx.x;
    sW[(tid >> 4) * 16 + (tid & 15)] = W4[tid];
    sW[(16 + (tid >> 4)) * 16 + (tid & 15)] = W4[256 + tid];
    __syncthreads();
    int c = tid & 15;
    int r = blockIdx.x * 16 + (tid >> 4);
    float z0 = A[(size_t)r * 32 + c];
    float z1 = A[(size_t)r * 32 + 16 + c];
    float a = 0.f;
#pragma unroll
    for (int k = 0; k < 16; k++) {
        a += __shfl_sync(0xffffffffu, z0, k, 16) * sW[k * 16 + c];
        a += __shfl_sync(0xffffffffu, z1, k, 16) * sW[(16 + k) * 16 + c];
    }
    Yh[(size_t)r * 16 + c] = a;
}

// ---------------- node SpMM (+relu, + optional partial gate dot) ----------------
// block = 256 = 2 rows x 128 cols. pgate: if non-null, accumulate dot(out_row, pgate)
// into snOut[row] via per-warp atomicAdd.
__global__ void k_node_spmm(const float* __restrict__ Y, const float* __restrict__ bias,
                            const float* __restrict__ se, float* __restrict__ out,
                            int ldo, int do_relu,
                            const float* __restrict__ pgate, float* __restrict__ snOut) {
    int row = blockIdx.x * 2 + (threadIdx.x >> 7);
    int c = threadIdx.x & 127;
    int n = g_vn[row]; if (n > ELLW) n = ELLW;
    int base = row * ELLW;
    float acc = bias[c];
    for (int i = 0; i < n; i++) {
        int col = g_vcol[base + i];
        float val = g_vval[base + i];
        float mult;
        if (col == row) {
            mult = 1.f;
        } else {
            int cnt = g_scnt[base + i];
            if (cnt > MAXPAR) cnt = MAXPAR;
            mult = 0.f;
            for (int q = 0; q < cnt; q++) mult += se[g_eid[(base + i) * MAXPAR + q]];
        }
        acc += val * mult * Y[(size_t)col * NH + c];
    }
    if (do_relu) acc = fmaxf(acc, 0.f);
    out[(size_t)row * ldo + c] = acc;
    if (pgate) {
        float dp = acc * pgate[c];
        for (int o = 16; o; o >>= 1) dp += __shfl_xor_sync(0xffffffffu, dp, o);
        if ((threadIdx.x & 31) == 0) atomicAdd(&snOut[row], dp);
    }
}

// ---------------- edge SpMM (+relu, + gate dot) ----------------
// gmode: 0 none; 1 atomicAdd partial (se3, p covers cols 0..15); 2 direct write (se5)
__global__ void k_edge_spmm(const float* __restrict__ Yh, const float* __restrict__ bias,
                            const unsigned* __restrict__ cmax, float* __restrict__ out,
                            int ldo, const float* __restrict__ p, float* __restrict__ seOut,
                            int gmode) {
    int t = blockIdx.x * blockDim.x + threadIdx.x;
    int r = t >> 4;
    int c = t & 15;
    if (r >= N_EDGES) return;
    int n = g_en[r]; if (n > ELLW) n = ELLW;
    size_t base = (size_t)r * ELLW;
    float acc = bias[c];
    for (int i = 0; i < n; i++) {
        int f = g_ecol[base + i];
        float w = g_adjEv[base + i] / __uint_as_float(cmax[f]);
        acc += w * Yh[(size_t)f * FE + c];
    }
    acc = fmaxf(acc, 0.f);
    out[(size_t)r * ldo + c] = acc;
    if (gmode) {
        float dp = acc * p[c];
        for (int o = 8; o; o >>= 1) dp += __shfl_xor_sync(0xffffffffu, dp, o, 16);
        if (c == 0) {
            if (gmode == 1) atomicAdd(&seOut[r], dp);
            else            seOut[r] = dp;
        }
    }
}

// ---------------- host ----------------
extern "C" void kernel_launch(void* const* d_in, const int* in_sizes, int n_in,
                              void* d_out, int out_size) {
    const float* X    = (const float*)d_in[0];
    const float* Z    = (const float*)d_in[1];
    const float* adjE = (const float*)d_in[2];
    const float* adjV = (const float*)d_in[3];
    const float* T    = (const float*)d_in[4];
    const float* W1  = (const float*)d_in[5];
    const float* p1  = (const float*)d_in[6];
    const float* b1  = (const float*)d_in[7];
    const float* Wf1 = (const float*)d_in[8];
    const float* g1  = (const float*)d_in[9];
    const float* be1 = (const float*)d_in[10];
    const float* W2  = (const float*)d_in[11];
    const float* p2  = (const float*)d_in[12];
    const float* b2  = (const float*)d_in[13];
    const float* Wf2 = (const float*)d_in[14];
    const float* g2  = (const float*)d_in[15];
    const float* be2 = (const float*)d_in[16];
    const float* W3  = (const float*)d_in[17];
    const float* p3  = (const float*)d_in[18];
    const float* b3  = (const float*)d_in[19];
    const float* W4  = (const float*)d_in[20];
    const float* p4  = (const float*)d_in[21];
    const float* b4  = (const float*)d_in[22];
    const float* W5  = (const float*)d_in[23];
    const float* p5  = (const float*)d_in[24];
    const float* b5  = (const float*)d_in[25];
    float* out = (float*)d_out;

    float *pY, *ptmpN, *pX1F1, *pX3, *pYh, *pZ2F2, *pZ4;
    float *pse1, *pse3, *pse5, *psn2, *psn4;
    unsigned *pcm2, *pcm4;
    cudaGetSymbolAddress((void**)&pY, g_Y);
    cudaGetSymbolAddress((void**)&ptmpN, g_tmpN);
    cudaGetSymbolAddress((void**)&pX1F1, g_X1F1);
    cudaGetSymbolAddress((void**)&pX3, g_X3);
    cudaGetSymbolAddress((void**)&pYh, g_Yh);
    cudaGetSymbolAddress((void**)&pZ2F2, g_Z2F2);
    cudaGetSymbolAddress((void**)&pZ4, g_Z4);
    cudaGetSymbolAddress((void**)&pse1, g_se1);
    cudaGetSymbolAddress((void**)&pse3, g_se3);
    cudaGetSymbolAddress((void**)&pse5, g_se5);
    cudaGetSymbolAddress((void**)&psn2, g_sn2);
    cudaGetSymbolAddress((void**)&psn4, g_sn4);
    cudaGetSymbolAddress((void**)&pcm2, g_cmax2);
    cudaGetSymbolAddress((void**)&pcm4, g_cmax4);

    // ---- structure + scan-independent work first ----
    k_init<<<348, 256>>>();
    k_edge_mlp2<<<256, 256>>>(Z, W2, Wf2, g2, be2, p1, p3, pYh, pZ2F2); // Yh, F2, se1, se3+
    k_gemmRB<<<dim3(128, 2), 256>>>(X, W1, Wf1, pY, ptmpN, FV);          // X@W1, X@Wf1
    k_ln_relu<<<256, 256>>>(ptmpN, g1, be1, p2, pX1F1 + NH);             // F1, sn2+
    k_scan_all<<<2048, 256>>>((const float4*)T, (const float4*)adjV, (const float4*)adjE);
    k_link_ecoef<<<16, 256>>>();

    // ---- layer 1: X1 (+sn2 partial) ----
    k_node_spmm<<<1024, 256>>>(pY, b1, pse1, pX1F1, 2 * NH, 1, p2, psn2);

    // ---- layer 2: edge vals + Z2 (+se3 partial) ----
    k_edge_vals<<<640, 256>>>(psn2, pcm2);
    k_edge_spmm<<<256, 256>>>(pYh, b2, pcm2, pZ2F2, 2 * FE, p3, pse3, 1);

    // ---- layer 3: gemm + X3 (+sn4 partial) ----
    k_gemmRB<<<dim3(128, 1), 256>>>(pX1F1, W3, W3, ptmpN, ptmpN, 2 * NH);
    k_node_spmm<<<1024, 256>>>(ptmpN, b3, pse3, pX3, NH, 1, p4, psn4);

    // ---- layer 4: mlp + vals + Z4 (+se5 direct) ----
    k_edge_mlp4<<<256, 256>>>(pZ2F2, W4, pYh);
    k_edge_vals<<<640, 256>>>(psn4, pcm4);
    k_edge_spmm<<<256, 256>>>(pYh, b4, pcm4, pZ4, FE, p5, pse5, 2);

    // ---- layer 5: gemm + out (no relu, no gate) ----
    k_gemmRB<<<dim3(128, 1), 256>>>(pX3, W5, W5, ptmpN, ptmpN, NH);
    k_node_spmm<<<1024, 256>>>(ptmpN, b5, pse5, out, NC, 0, (const float*)0, (float*)0);
}